// round 15
// baseline (speedup 1.0000x reference)
#include <cuda_runtime.h>

// x: (128, 32, 2, 64, 64) fp32 -> 4096 tiles of (2, 64, 64).
// plaq[i][j] = t0[i][j] + t1[(i+1)%64][j] - t0[i][(j+1)%64] - t1[i][j]
// out[tile] = mean(cos(plaq))
//
// R9 policy (t0 streamed via __ldcs, t1 default -> L2-resident across graph
// replays) + t1 staged through smem so its rolled re-read (row i+1) is an
// LDS instead of a second L2 read. Warm-loop L2 traffic per replay drops
// 192 MB -> 128 MB (t1 read from L2 exactly once), relieving the LTS cap
// that bounds the R9 steady state. t0 stays register-direct; j+1 roll stays
// in-register via lane shuffle.

#define THREADS 256

__global__ __launch_bounds__(THREADS, 8) void plaq_trace_smem1_kernel(
    const float4* __restrict__ x4, float* __restrict__ out)
{
    const int t = blockIdx.x;
    const float4* __restrict__ t0 = x4 + (size_t)t * 2048;  // 1024 float4 each
    const float4* __restrict__ t1 = t0 + 1024;

    const int tid  = threadIdx.x;
    const int lane = tid & 31;
    const int wid  = tid >> 5;
    const int src  = (lane & 16) | ((lane + 1) & 15);  // right-neighbor lane

    __shared__ float4 s1[1024];                  // t1 tile, 16 KB
    __shared__ float  warp_sums[THREADS / 32];

    float4 A0[4];

    // Front-batched loads: 4x t0 (streamed, kept in regs) + 4x t1 (default
    // policy -> L2-resident across replays) staged to smem.
    #pragma unroll
    for (int k = 0; k < 4; k++) {
        const int g = tid + k * THREADS;         // float4 group 0..1023
        A0[k] = __ldcs(t0 + g);
        s1[g] = t1[g];                           // single L2 read of t1
    }
    __syncthreads();

    float sum = 0.0f;
    #pragma unroll
    for (int k = 0; k < 4; k++) {
        const int g  = tid + k * THREADS;
        const int i  = g >> 4;                   // row 0..63
        const int g1 = (((i + 1) & 63) << 4) | (g & 15);

        const float4 A1 = s1[g];                 // LDS.128, stride-1
        const float4 B1 = s1[g1];                // LDS.128, stride-1
        const float nx = __shfl_sync(0xFFFFFFFFu, A0[k].x, src);

        sum += __cosf(A0[k].x + B1.x - A0[k].y - A1.x);
        sum += __cosf(A0[k].y + B1.y - A0[k].z - A1.y);
        sum += __cosf(A0[k].z + B1.z - A0[k].w - A1.z);
        sum += __cosf(A0[k].w + B1.w - nx      - A1.w);
    }

    #pragma unroll
    for (int off = 16; off > 0; off >>= 1)
        sum += __shfl_xor_sync(0xFFFFFFFFu, sum, off);

    if (lane == 0) warp_sums[wid] = sum;
    __syncthreads();

    if (wid == 0) {
        float s = (lane < (THREADS / 32)) ? warp_sums[lane] : 0.0f;
        #pragma unroll
        for (int off = 4; off > 0; off >>= 1)
            s += __shfl_xor_sync(0xFFFFFFFFu, s, off);
        if (lane == 0) out[t] = s * (1.0f / 4096.0f);
    }
}

extern "C" void kernel_launch(void* const* d_in, const int* in_sizes, int n_in,
                              void* d_out, int out_size)
{
    const float4* x4 = (const float4*)d_in[0];
    float* out = (float*)d_out;
    plaq_trace_smem1_kernel<<<4096, THREADS>>>(x4, out);
}

// round 16
// speedup vs baseline: 1.1345x; 1.1345x over previous
#include <cuda_runtime.h>

// x: (128, 32, 2, 64, 64) fp32 -> 4096 tiles of (2, 64, 64).
// plaq[i][j] = t0[i][j] + t1[(i+1)%64][j] - t0[i][(j+1)%64] - t1[i][j]
// out[tile] = mean(cos(plaq))
//
// R9 winning shape (front-batched loads, __ldcs-streamed t0 / default t1 so
// t1 stays L2-resident across graph replays, one CTA per tile, max occupancy)
// with telescoped t1 loads: 512 threads/CTA, each thread owns TWO CONSECUTIVE
// ROWS of one column-group, so the row-rolled t1 read of row u is the direct
// t1 read of row u+1 -> 3 t1 loads instead of 4 (5 loads/thread total, -17%
// LDG + L1 wavefronts; DRAM/L2 bytes unchanged). j+1 roll stays in-register
// via lane shuffle (half-warp = 16 col-groups of one row pair).

#define THREADS 512

__global__ __launch_bounds__(THREADS, 4) void plaq_trace_rowreuse_kernel(
    const float4* __restrict__ x4, float* __restrict__ out)
{
    const int t = blockIdx.x;
    const float4* __restrict__ t0 = x4 + (size_t)t * 2048;  // 1024 float4 each
    const float4* __restrict__ t1 = t0 + 1024;

    const int tid  = threadIdx.x;
    const int lane = tid & 31;
    const int wid  = tid >> 5;
    const int jg   = tid & 15;          // column group 0..15
    const int r0   = (tid >> 4) * 2;    // first of two consecutive rows
    const int src  = (lane & 16) | ((lane + 1) & 15);  // right-neighbor lane

    // Front-batched independent loads: 2x t0 (streamed) + 3x t1 (default).
    float4 A0[2], A1[3];
    #pragma unroll
    for (int u = 0; u < 2; u++)
        A0[u] = __ldcs(t0 + (r0 + u) * 16 + jg);
    #pragma unroll
    for (int u = 0; u < 3; u++)
        A1[u] = t1[(((r0 + u) & 63) << 4) + jg];   // only u=2 can wrap (62->0? no: 64->0)

    float sum = 0.0f;
    #pragma unroll
    for (int u = 0; u < 2; u++) {
        const float4 a0 = A0[u];
        const float4 a1 = A1[u];
        const float4 b1 = A1[u + 1];               // telescoped row roll
        const float nx = __shfl_sync(0xFFFFFFFFu, a0.x, src);
        sum += __cosf(a0.x + b1.x - a0.y - a1.x);
        sum += __cosf(a0.y + b1.y - a0.z - a1.y);
        sum += __cosf(a0.z + b1.z - a0.w - a1.z);
        sum += __cosf(a0.w + b1.w - nx   - a1.w);
    }

    #pragma unroll
    for (int off = 16; off > 0; off >>= 1)
        sum += __shfl_xor_sync(0xFFFFFFFFu, sum, off);

    __shared__ float warp_sums[THREADS / 32];
    if (lane == 0) warp_sums[wid] = sum;
    __syncthreads();

    if (wid == 0) {
        float s = (lane < (THREADS / 32)) ? warp_sums[lane] : 0.0f;
        #pragma unroll
        for (int off = 8; off > 0; off >>= 1)
            s += __shfl_xor_sync(0xFFFFFFFFu, s, off);
        if (lane == 0) out[t] = s * (1.0f / 4096.0f);
    }
}

extern "C" void kernel_launch(void* const* d_in, const int* in_sizes, int n_in,
                              void* d_out, int out_size)
{
    const float4* x4 = (const float4*)d_in[0];
    float* out = (float*)d_out;
    plaq_trace_rowreuse_kernel<<<4096, THREADS>>>(x4, out);
}